// round 2
// baseline (speedup 1.0000x reference)
#include <cuda_runtime.h>

#define DCH 128
#define TILE 64
#define KB 32
#define WPAD 129

struct GArgs {
  const float* X; int rows;
  const float* W; int ldW; int colOff;
  const float* gnw; const float* gnb; int relu;
  const float* add1; const int* idx1;
  const float* add2; const int* idx2;
  const float* res;
  float* Y;
  float* atomY; const int* atomIdx;
  const float* actor_ctrs; const float* node_ctrs;
  const int* hi; const int* wi;
  const float* Wd1; const float* bd1;
};

// Scratch (alloc-free: __device__ globals)
__device__ float g_edge[150000 * 128];   // edge features (d, then cf in-place)
__device__ float g_acc[4000 * 128];      // scatter accumulator (agts@Wa^T + sum cf)
__device__ float g_qc[4000 * 128];       // per-actor q-contribution to Wc1
__device__ float g_nc[20000 * 128];      // per-node contribution to Wc1
__device__ float g_tmp[4000 * 128];      // small temp
__device__ float g_agts[4000 * 128];     // layer-1 output actors

// Generic fused [rows,128] x [128(out),128(in slab of ldW)] GEMM.
// Thread layout: 256 threads; warp w owns rows w*8..w*8+7; lane owns cols
// {lane, lane+32, lane+64, lane+96}  (conflict-free smem W reads, coalesced I/O).
// Epilogue options: gathered pre-adds, GroupNorm(1 group) via warp shfl,
// relu, residual+relu, store or atomicAdd-scatter.
// D1MODE: input row = relu(ctr_d @ Wd1^T + bd1) computed on the fly.
template <bool D1MODE>
__global__ void __launch_bounds__(256) gemm128_kernel(GArgs a) {
  __shared__ float Wt[KB * WPAD];    // Wt[k][j], padded: stores & reads conflict-free
  __shared__ float Xs[TILE * KB];    // Xs[row][k]
  __shared__ float cxs[TILE];
  __shared__ float cys[TILE];

  const int tid  = threadIdx.x;
  const int warp = tid >> 5;
  const int lane = tid & 31;
  const int row0 = blockIdx.x * TILE;

  if (D1MODE) {
    if (tid < TILE) {
      int gr = row0 + tid;
      float cx = 0.f, cy = 0.f;
      if (gr < a.rows) {
        int h = a.hi[gr], w = a.wi[gr];
        cx = a.actor_ctrs[2 * h]     - a.node_ctrs[2 * w];
        cy = a.actor_ctrs[2 * h + 1] - a.node_ctrs[2 * w + 1];
      }
      cxs[tid] = cx;
      cys[tid] = cy;
    }
  }

  float acc[8][4];
#pragma unroll
  for (int r = 0; r < 8; r++)
#pragma unroll
    for (int c = 0; c < 4; c++) acc[r][c] = 0.f;

#pragma unroll 1
  for (int kb = 0; kb < 4; kb++) {
    __syncthreads();
    // Load W slab transposed: Wt[k][j] = W[j*ldW + colOff + kb*32 + k]
    // gmem coalesced (lanes -> consecutive k); smem stores conflict-free (WPAD=129).
    for (int i = tid; i < DCH * KB; i += 256) {
      int k = i & (KB - 1), j = i >> 5;
      Wt[k * WPAD + j] = a.W[(size_t)j * a.ldW + a.colOff + kb * KB + k];
    }
    if (D1MODE) {
      for (int i = tid; i < TILE * KB; i += 256) {
        int r = i >> 5, k = i & (KB - 1);
        int kg = kb * KB + k;
        float v = fmaf(cxs[r], a.Wd1[2 * kg], fmaf(cys[r], a.Wd1[2 * kg + 1], a.bd1[kg]));
        Xs[r * KB + k] = fmaxf(v, 0.f);
      }
    } else {
      for (int i = tid; i < TILE * (KB / 4); i += 256) {
        int r = i >> 3, k4 = i & 7;
        int gr = row0 + r;
        float4 v = make_float4(0.f, 0.f, 0.f, 0.f);
        if (gr < a.rows)
          v = *(const float4*)(a.X + (size_t)gr * DCH + kb * KB + k4 * 4);
        *(float4*)&Xs[r * KB + k4 * 4] = v;
      }
    }
    __syncthreads();
#pragma unroll 8
    for (int k = 0; k < KB; k++) {
      float w0 = Wt[k * WPAD + lane];
      float w1 = Wt[k * WPAD + lane + 32];
      float w2 = Wt[k * WPAD + lane + 64];
      float w3 = Wt[k * WPAD + lane + 96];
#pragma unroll
      for (int r = 0; r < 8; r++) {
        float x = Xs[(warp * 8 + r) * KB + k];
        acc[r][0] = fmaf(x, w0, acc[r][0]);
        acc[r][1] = fmaf(x, w1, acc[r][1]);
        acc[r][2] = fmaf(x, w2, acc[r][2]);
        acc[r][3] = fmaf(x, w3, acc[r][3]);
      }
    }
  }

  const int rbase = row0 + warp * 8;

  // Gathered pre-adds (before GroupNorm): + add1[idx1[r]] + add2[idx2[r]]
  if (a.add1) {
#pragma unroll
    for (int r = 0; r < 8; r++) {
      int gr = rbase + r;
      if (gr < a.rows) {
        const float* p1 = a.add1 + (size_t)a.idx1[gr] * DCH + lane;
        const float* p2 = a.add2 + (size_t)a.idx2[gr] * DCH + lane;
#pragma unroll
        for (int c = 0; c < 4; c++) acc[r][c] += p1[32 * c] + p2[32 * c];
      }
    }
  }

  // GroupNorm(num_groups=1) over 128 channels per row
  if (a.gnw) {
    float gw[4], gb[4];
#pragma unroll
    for (int c = 0; c < 4; c++) {
      gw[c] = a.gnw[lane + 32 * c];
      gb[c] = a.gnb[lane + 32 * c];
    }
#pragma unroll
    for (int r = 0; r < 8; r++) {
      float s = acc[r][0] + acc[r][1] + acc[r][2] + acc[r][3];
      float q = fmaf(acc[r][0], acc[r][0],
                fmaf(acc[r][1], acc[r][1],
                fmaf(acc[r][2], acc[r][2], acc[r][3] * acc[r][3])));
#pragma unroll
      for (int o = 16; o > 0; o >>= 1) {
        s += __shfl_xor_sync(0xffffffffu, s, o);
        q += __shfl_xor_sync(0xffffffffu, q, o);
      }
      float m   = s * (1.f / DCH);
      float var = q * (1.f / DCH) - m * m;
      float inv = rsqrtf(var + 1e-5f);
#pragma unroll
      for (int c = 0; c < 4; c++)
        acc[r][c] = fmaf((acc[r][c] - m) * inv, gw[c], gb[c]);
    }
  }

  if (a.relu) {
#pragma unroll
    for (int r = 0; r < 8; r++)
#pragma unroll
      for (int c = 0; c < 4; c++) acc[r][c] = fmaxf(acc[r][c], 0.f);
  }

#pragma unroll
  for (int r = 0; r < 8; r++) {
    int gr = rbase + r;
    if (gr >= a.rows) continue;
    if (a.res) {  // out = relu(x + res)
      const float* rp = a.res + (size_t)gr * DCH + lane;
#pragma unroll
      for (int c = 0; c < 4; c++) acc[r][c] = fmaxf(acc[r][c] + rp[32 * c], 0.f);
    }
    if (a.atomY) {
      float* dst = a.atomY + (size_t)a.atomIdx[gr] * DCH + lane;
#pragma unroll
      for (int c = 0; c < 4; c++) atomicAdd(dst + 32 * c, acc[r][c]);
    } else {
      float* dst = a.Y + (size_t)gr * DCH + lane;
#pragma unroll
      for (int c = 0; c < 4; c++) dst[32 * c] = acc[r][c];
    }
  }
}

// y = relu(gn(x)) row-wise, one warp per row
__global__ void __launch_bounds__(256)
rownorm_relu_kernel(const float* X, float* Y, const float* gnw, const float* gnb, int rows) {
  int warp = threadIdx.x >> 5, lane = threadIdx.x & 31;
  int row = blockIdx.x * 8 + warp;
  if (row >= rows) return;
  float4 v = *(const float4*)(X + (size_t)row * DCH + lane * 4);
  float s = v.x + v.y + v.z + v.w;
  float q = v.x * v.x + v.y * v.y + v.z * v.z + v.w * v.w;
#pragma unroll
  for (int o = 16; o > 0; o >>= 1) {
    s += __shfl_xor_sync(0xffffffffu, s, o);
    q += __shfl_xor_sync(0xffffffffu, q, o);
  }
  float m = s * (1.f / DCH), var = q * (1.f / DCH) - m * m;
  float inv = rsqrtf(var + 1e-5f);
  float4 gw = *(const float4*)(gnw + lane * 4);
  float4 gb = *(const float4*)(gnb + lane * 4);
  float4 o4;
  o4.x = fmaxf(fmaf((v.x - m) * inv, gw.x, gb.x), 0.f);
  o4.y = fmaxf(fmaf((v.y - m) * inv, gw.y, gb.y), 0.f);
  o4.z = fmaxf(fmaf((v.z - m) * inv, gw.z, gb.z), 0.f);
  o4.w = fmaxf(fmaf((v.w - m) * inv, gw.w, gb.w), 0.f);
  *(float4*)(Y + (size_t)row * DCH + lane * 4) = o4;
}

extern "C" void kernel_launch(void* const* d_in, const int* in_sizes, int n_in,
                              void* d_out, int out_size) {
  const float* actors     = (const float*)d_in[0];
  const float* nodes      = (const float*)d_in[1];
  const float* actor_ctrs = (const float*)d_in[2];
  const float* node_ctrs  = (const float*)d_in[3];
  const int*   hi         = (const int*)d_in[4];
  const int*   wi         = (const int*)d_in[5];
  const float* Wd1   = (const float*)d_in[6];
  const float* bd1   = (const float*)d_in[7];
  const float* Wd2   = (const float*)d_in[8];
  const float* gnd2w = (const float*)d_in[9];
  const float* gnd2b = (const float*)d_in[10];
  const float* Wq    = (const float*)d_in[11];
  const float* gnqw  = (const float*)d_in[12];
  const float* gnqb  = (const float*)d_in[13];
  const float* Wc1   = (const float*)d_in[14];
  const float* gnc1w = (const float*)d_in[15];
  const float* gnc1b = (const float*)d_in[16];
  const float* Wc2   = (const float*)d_in[17];
  const float* Wa    = (const float*)d_in[18];
  const float* gnnw  = (const float*)d_in[19];
  const float* gnnb  = (const float*)d_in[20];
  const float* Wl    = (const float*)d_in[21];
  const float* gnlw  = (const float*)d_in[22];
  const float* gnlb  = (const float*)d_in[23];

  const int M = in_sizes[0] / DCH;
  const int N = in_sizes[1] / DCH;
  const int E = in_sizes[4];

  float *edge, *accb, *qc, *nc, *tmp, *agts1;
  cudaGetSymbolAddress((void**)&edge,  g_edge);
  cudaGetSymbolAddress((void**)&accb,  g_acc);
  cudaGetSymbolAddress((void**)&qc,    g_qc);
  cudaGetSymbolAddress((void**)&nc,    g_nc);
  cudaGetSymbolAddress((void**)&tmp,   g_tmp);
  cudaGetSymbolAddress((void**)&agts1, g_agts);

  const int mb = (M + TILE - 1) / TILE;
  const int nb = (N + TILE - 1) / TILE;
  const int eb = (E + TILE - 1) / TILE;

  const float* agts_in = actors;
  for (int L = 0; L < 2; L++) {
    const float* Wd1L = Wd1 + L * DCH * 2;
    const float* bd1L = bd1 + L * DCH;
    const float* Wd2L = Wd2 + L * DCH * DCH;
    const float* WqL  = Wq  + L * DCH * DCH;
    const float* Wc1L = Wc1 + L * DCH * 3 * DCH;
    const float* Wc2L = Wc2 + L * DCH * DCH;
    const float* WaL  = Wa  + L * DCH * DCH;
    const float* WlL  = Wl  + L * DCH * DCH;
    float* outp = (L == 0) ? agts1 : (float*)d_out;

    GArgs a;

    // 1: tmp = relu(gn(agts @ Wq^T))   (computed on M rows, gathered later)
    a = GArgs{}; a.X = agts_in; a.rows = M; a.W = WqL; a.ldW = DCH; a.colOff = 0;
    a.gnw = gnqw + L * DCH; a.gnb = gnqb + L * DCH; a.relu = 1; a.Y = tmp;
    gemm128_kernel<false><<<mb, 256>>>(a);

    // 2: qc = tmp @ Wc1[:,128:256]^T   (per-actor Wc1 contribution)
    a = GArgs{}; a.X = tmp; a.rows = M; a.W = Wc1L; a.ldW = 3 * DCH; a.colOff = DCH;
    a.Y = qc;
    gemm128_kernel<false><<<mb, 256>>>(a);

    // 3: nc = nodes @ Wc1[:,256:384]^T (per-node Wc1 contribution)
    a = GArgs{}; a.X = nodes; a.rows = N; a.W = Wc1L; a.ldW = 3 * DCH; a.colOff = 2 * DCH;
    a.Y = nc;
    gemm128_kernel<false><<<nb, 256>>>(a);

    // 4: acc = agts @ Wa^T
    a = GArgs{}; a.X = agts_in; a.rows = M; a.W = WaL; a.ldW = DCH; a.Y = accb;
    gemm128_kernel<false><<<mb, 256>>>(a);

    // 5: edge = relu(gn(relu(ctr_d @ Wd1^T + bd1) @ Wd2^T))   [E rows]
    a = GArgs{}; a.rows = E; a.W = Wd2L; a.ldW = DCH;
    a.gnw = gnd2w + L * DCH; a.gnb = gnd2b + L * DCH; a.relu = 1; a.Y = edge;
    a.actor_ctrs = actor_ctrs; a.node_ctrs = node_ctrs; a.hi = hi; a.wi = wi;
    a.Wd1 = Wd1L; a.bd1 = bd1L;
    gemm128_kernel<true><<<eb, 256>>>(a);

    // 6: edge = relu(gn(edge @ Wc1[:,0:128]^T + qc[hi] + nc[wi]))  (in-place)
    a = GArgs{}; a.X = edge; a.rows = E; a.W = Wc1L; a.ldW = 3 * DCH; a.colOff = 0;
    a.add1 = qc; a.idx1 = hi; a.add2 = nc; a.idx2 = wi;
    a.gnw = gnc1w + L * DCH; a.gnb = gnc1b + L * DCH; a.relu = 1; a.Y = edge;
    gemm128_kernel<false><<<eb, 256>>>(a);

    // 7: acc[hi] += edge @ Wc2^T       (atomic scatter-add)
    a = GArgs{}; a.X = edge; a.rows = E; a.W = Wc2L; a.ldW = DCH;
    a.atomY = accb; a.atomIdx = hi;
    gemm128_kernel<false><<<eb, 256>>>(a);

    // 8: tmp = relu(gn(acc))
    rownorm_relu_kernel<<<(M + 7) / 8, 256>>>(accb, tmp, gnnw + L * DCH, gnnb + L * DCH, M);

    // 9: out = relu(gn(tmp @ Wl^T) + agts_in)
    a = GArgs{}; a.X = tmp; a.rows = M; a.W = WlL; a.ldW = DCH;
    a.gnw = gnlw + L * DCH; a.gnb = gnlb + L * DCH; a.relu = 0; a.res = agts_in;
    a.Y = outp;
    gemm128_kernel<false><<<mb, 256>>>(a);

    agts_in = agts1;
  }
}

// round 4
// speedup vs baseline: 1.3638x; 1.3638x over previous
#include <cuda_runtime.h>
#include <cuda_bf16.h>
#include <cstdint>

#define DCH 128
#define TM  128
#define LDP 68            // pairs per row in smem (uint2 units); stride 136 words == 8 mod 32

// ---------------- scratch (alloc-free) ----------------
__device__ float g_edge[150000 * 128];
__device__ float g_acc[4000 * 128];
__device__ float g_qc[4000 * 128];
__device__ float g_nc[20000 * 128];
__device__ float g_tmp[4000 * 128];
__device__ float g_agts[4000 * 128];

// smem layout (bytes)
#define OF_A   0
#define OF_B   (128 * LDP * 8)            // 69632
#define OF_SUM (2 * 128 * LDP * 8)        // 139264 : ps[2][128], pq[2][128]
#define SMEM_DYN (OF_SUM + 2048 + 256)

struct GArgs {
  const float* X; int rows;
  const float* W; int ldW; int colOff;
  const float* gnw; const float* gnb; int relu;
  const float* add1; const int* idx1;
  const float* add2; const int* idx2;
  const float* res;
  float* Y;
  float* atomY; const int* atomIdx;
  const float* actor_ctrs; const float* node_ctrs;
  const int* hi; const int* wi;
  const float* Wd1; const float* bd1;
};

__device__ __forceinline__ uint32_t smem_u32(const void* p) {
  uint32_t a;
  asm("{ .reg .u64 t; cvta.to.shared.u64 t, %1; cvt.u32.u64 %0, t; }" : "=r"(a) : "l"(p));
  return a;
}

#define LDS64(hi, lo, addr) \
  asm volatile("ld.shared.v2.u32 {%0,%1}, [%2];" : "=r"(hi), "=r"(lo) : "r"(addr))

__device__ __forceinline__ void mma_bf16(float c[4], const uint32_t a[4],
                                         uint32_t b0, uint32_t b1) {
  asm volatile(
    "mma.sync.aligned.m16n8k16.row.col.f32.bf16.bf16.f32 "
    "{%0,%1,%2,%3}, {%4,%5,%6,%7}, {%8,%9}, {%0,%1,%2,%3};"
    : "+f"(c[0]), "+f"(c[1]), "+f"(c[2]), "+f"(c[3])
    : "r"(a[0]), "r"(a[1]), "r"(a[2]), "r"(a[3]), "r"(b0), "r"(b1));
}

// pack 4 floats into 2 smem pair-words: {hi(x,y), lo(x,y)}, {hi(z,w), lo(z,w)}
__device__ __forceinline__ void pack4(float x, float y, float z, float w, uint4& out) {
  __nv_bfloat16 hx = __float2bfloat16(x), hy = __float2bfloat16(y);
  __nv_bfloat16 hz = __float2bfloat16(z), hw = __float2bfloat16(w);
  __nv_bfloat16 lx = __float2bfloat16(x - __bfloat162float(hx));
  __nv_bfloat16 ly = __float2bfloat16(y - __bfloat162float(hy));
  __nv_bfloat16 lz = __float2bfloat16(z - __bfloat162float(hz));
  __nv_bfloat16 lw = __float2bfloat16(w - __bfloat162float(hw));
  out.x = (uint32_t)__bfloat16_as_ushort(hx) | ((uint32_t)__bfloat16_as_ushort(hy) << 16);
  out.y = (uint32_t)__bfloat16_as_ushort(lx) | ((uint32_t)__bfloat16_as_ushort(ly) << 16);
  out.z = (uint32_t)__bfloat16_as_ushort(hz) | ((uint32_t)__bfloat16_as_ushort(hw) << 16);
  out.w = (uint32_t)__bfloat16_as_ushort(lz) | ((uint32_t)__bfloat16_as_ushort(lw) << 16);
}

// Fused tensor-core GEMM: out[rows,128] = X[rows,128] @ W[:,colOff:+128]^T
// 3-term bf16 hi/lo split on HMMA (mma.sync), fp32 accum.
template <bool D1MODE>
__global__ void __launch_bounds__(256, 1) tgemm_kernel(GArgs a) {
  extern __shared__ char smem[];
  const uint32_t sb = smem_u32(smem);
  const int tid = threadIdx.x;
  const int warp = tid >> 5;
  const int lane = tid & 31;
  const int row0 = blockIdx.x * TM;

  // ---------------- load phase ----------------
  {
    // B tile: W rows j = tid>>1, half = tid&1 covers 64 cols
    const int j = tid >> 1, half = tid & 1;
    const float* p = a.W + (size_t)j * a.ldW + a.colOff + half * 64;
    uint32_t bbase = sb + OF_B + (j * LDP + half * 32) * 8;
#pragma unroll
    for (int i = 0; i < 16; i++) {
      float4 v = *(const float4*)(p + 4 * i);
      uint4 o;
      pack4(v.x, v.y, v.z, v.w, o);
      *(uint4*)(smem + (bbase - sb) + 16 * i) = o;
    }
    // A tile
    const int row = j;
    const int gr = row0 + row;
    uint32_t abase = sb + OF_A + (row * LDP + half * 32) * 8;
    if (D1MODE) {
      float cx = 0.f, cy = 0.f;
      if (gr < a.rows) {
        int h = a.hi[gr], w = a.wi[gr];
        cx = a.actor_ctrs[2 * h]     - a.node_ctrs[2 * w];
        cy = a.actor_ctrs[2 * h + 1] - a.node_ctrs[2 * w + 1];
      }
#pragma unroll
      for (int i = 0; i < 16; i++) {
        float vv[4];
#pragma unroll
        for (int q = 0; q < 4; q++) {
          int k = half * 64 + 4 * i + q;
          vv[q] = fmaxf(fmaf(cx, a.Wd1[2 * k], fmaf(cy, a.Wd1[2 * k + 1], a.bd1[k])), 0.f);
        }
        uint4 o;
        pack4(vv[0], vv[1], vv[2], vv[3], o);
        *(uint4*)(smem + (abase - sb) + 16 * i) = o;
      }
    } else {
      const float* px = a.X + (size_t)gr * DCH + half * 64;
#pragma unroll
      for (int i = 0; i < 16; i++) {
        float4 v = make_float4(0.f, 0.f, 0.f, 0.f);
        if (gr < a.rows) v = *(const float4*)(px + 4 * i);
        uint4 o;
        pack4(v.x, v.y, v.z, v.w, o);
        *(uint4*)(smem + (abase - sb) + 16 * i) = o;
      }
    }
  }
  __syncthreads();

  // ---------------- mainloop ----------------
  const int mw = warp & 3;        // 4 warps over M
  const int nw = warp >> 2;       // 2 warps over N
  const int rowb = mw * 32;
  const int cwb = nw * 64;
  const int g  = lane >> 2;       // groupID
  const int tg = lane & 3;        // threadID in group

  float acc[2][8][4];
#pragma unroll
  for (int ms = 0; ms < 2; ms++)
#pragma unroll
    for (int ns = 0; ns < 8; ns++)
#pragma unroll
      for (int q = 0; q < 4; q++) acc[ms][ns][q] = 0.f;

  const uint32_t Ab = sb + OF_A;
  const uint32_t Bb = sb + OF_B;

#pragma unroll
  for (int ks = 0; ks < 8; ks++) {
    uint32_t ah[2][4], al[2][4];
#pragma unroll
    for (int ms = 0; ms < 2; ms++) {
      const int r0 = rowb + ms * 16 + g;
      LDS64(ah[ms][0], al[ms][0], Ab + ((r0)     * LDP + ks * 8 + tg)     * 8);
      LDS64(ah[ms][1], al[ms][1], Ab + ((r0 + 8) * LDP + ks * 8 + tg)     * 8);
      LDS64(ah[ms][2], al[ms][2], Ab + ((r0)     * LDP + ks * 8 + tg + 4) * 8);
      LDS64(ah[ms][3], al[ms][3], Ab + ((r0 + 8) * LDP + ks * 8 + tg + 4) * 8);
    }
#pragma unroll
    for (int ns = 0; ns < 8; ns++) {
      const int n = cwb + ns * 8 + g;
      uint32_t bh0, bl0, bh1, bl1;
      LDS64(bh0, bl0, Bb + (n * LDP + ks * 8 + tg)     * 8);
      LDS64(bh1, bl1, Bb + (n * LDP + ks * 8 + tg + 4) * 8);
#pragma unroll
      for (int ms = 0; ms < 2; ms++) {
        mma_bf16(acc[ms][ns], ah[ms], bh0, bh1);
        mma_bf16(acc[ms][ns], ah[ms], bl0, bl1);
        mma_bf16(acc[ms][ns], al[ms], bh0, bh1);
      }
    }
  }

  // ---------------- epilogue ----------------
  // lane owns rows: rowb + ms*16 + h*8 + g   (ms,h in {0,1}) -> acc[ms][ns][2h+j]
  // lane owns cols: cwb + ns*8 + tg*2 + j
  const int c0 = cwb + tg * 2;

  // gather pre-adds (before GroupNorm)
  if (a.add1) {
#pragma unroll
    for (int ms = 0; ms < 2; ms++)
#pragma unroll
      for (int h = 0; h < 2; h++) {
        const int gr = row0 + rowb + ms * 16 + h * 8 + g;
        if (gr < a.rows) {
          const float* p1 = a.add1 + (size_t)a.idx1[gr] * DCH + c0;
          const float* p2 = a.add2 + (size_t)a.idx2[gr] * DCH + c0;
#pragma unroll
          for (int ns = 0; ns < 8; ns++) {
            float2 v1 = *(const float2*)(p1 + ns * 8);
            float2 v2 = *(const float2*)(p2 + ns * 8);
            acc[ms][ns][2 * h]     += v1.x + v2.x;
            acc[ms][ns][2 * h + 1] += v1.y + v2.y;
          }
        }
      }
  }

  if (a.gnw) {
    float* ps = (float*)(smem + OF_SUM);       // [2][128]
    float* pq = ps + 256;
    float sv[2][2], qv[2][2];
#pragma unroll
    for (int ms = 0; ms < 2; ms++)
#pragma unroll
      for (int h = 0; h < 2; h++) {
        float s = 0.f, q = 0.f;
#pragma unroll
        for (int ns = 0; ns < 8; ns++)
#pragma unroll
          for (int j = 0; j < 2; j++) {
            float v = acc[ms][ns][2 * h + j];
            s += v;
            q = fmaf(v, v, q);
          }
        // reduce across the 4 lanes sharing this row (same g)
        s += __shfl_xor_sync(0xffffffffu, s, 1);
        q += __shfl_xor_sync(0xffffffffu, q, 1);
        s += __shfl_xor_sync(0xffffffffu, s, 2);
        q += __shfl_xor_sync(0xffffffffu, q, 2);
        sv[ms][h] = s;
        qv[ms][h] = q;
        const int r = rowb + ms * 16 + h * 8 + g;
        if (tg == 0) { ps[nw * 128 + r] = s; pq[nw * 128 + r] = q; }
      }
    __syncthreads();
    // load gn params for owned cols
    float2 gwv[8], gbv[8];
#pragma unroll
    for (int ns = 0; ns < 8; ns++) {
      gwv[ns] = *(const float2*)(a.gnw + c0 + ns * 8);
      gbv[ns] = *(const float2*)(a.gnb + c0 + ns * 8);
    }
#pragma unroll
    for (int ms = 0; ms < 2; ms++)
#pragma unroll
      for (int h = 0; h < 2; h++) {
        const int r = rowb + ms * 16 + h * 8 + g;
        float s = sv[ms][h] + ps[(nw ^ 1) * 128 + r];
        float q = qv[ms][h] + pq[(nw ^ 1) * 128 + r];
        float m = s * (1.f / DCH);
        float var = q * (1.f / DCH) - m * m;
        float inv = rsqrtf(var + 1e-5f);
#pragma unroll
        for (int ns = 0; ns < 8; ns++) {
          acc[ms][ns][2 * h]     = fmaf((acc[ms][ns][2 * h]     - m) * inv, gwv[ns].x, gbv[ns].x);
          acc[ms][ns][2 * h + 1] = fmaf((acc[ms][ns][2 * h + 1] - m) * inv, gwv[ns].y, gbv[ns].y);
        }
      }
  }

  if (a.relu) {
#pragma unroll
    for (int ms = 0; ms < 2; ms++)
#pragma unroll
      for (int ns = 0; ns < 8; ns++)
#pragma unroll
        for (int q = 0; q < 4; q++) acc[ms][ns][q] = fmaxf(acc[ms][ns][q], 0.f);
  }

#pragma unroll
  for (int ms = 0; ms < 2; ms++)
#pragma unroll
    for (int h = 0; h < 2; h++) {
      const int gr = row0 + rowb + ms * 16 + h * 8 + g;
      if (gr >= a.rows) continue;
      if (a.res) {
        const float* rp = a.res + (size_t)gr * DCH + c0;
#pragma unroll
        for (int ns = 0; ns < 8; ns++) {
          float2 v = *(const float2*)(rp + ns * 8);
          acc[ms][ns][2 * h]     = fmaxf(acc[ms][ns][2 * h]     + v.x, 0.f);
          acc[ms][ns][2 * h + 1] = fmaxf(acc[ms][ns][2 * h + 1] + v.y, 0.f);
        }
      }
      if (a.atomY) {
        float* dst = a.atomY + (size_t)a.atomIdx[gr] * DCH + c0;
#pragma unroll
        for (int ns = 0; ns < 8; ns++) {
          atomicAdd(dst + ns * 8,     acc[ms][ns][2 * h]);
          atomicAdd(dst + ns * 8 + 1, acc[ms][ns][2 * h + 1]);
        }
      } else {
        float* dst = a.Y + (size_t)gr * DCH + c0;
#pragma unroll
        for (int ns = 0; ns < 8; ns++)
          *(float2*)(dst + ns * 8) =
              make_float2(acc[ms][ns][2 * h], acc[ms][ns][2 * h + 1]);
      }
    }
}

// y = relu(gn(x)) row-wise, one warp per row
__global__ void __launch_bounds__(256)
rownorm_relu_kernel(const float* X, float* Y, const float* gnw, const float* gnb, int rows) {
  int warp = threadIdx.x >> 5, lane = threadIdx.x & 31;
  int row = blockIdx.x * 8 + warp;
  if (row >= rows) return;
  float4 v = *(const float4*)(X + (size_t)row * DCH + lane * 4);
  float s = v.x + v.y + v.z + v.w;
  float q = v.x * v.x + v.y * v.y + v.z * v.z + v.w * v.w;
#pragma unroll
  for (int o = 16; o > 0; o >>= 1) {
    s += __shfl_xor_sync(0xffffffffu, s, o);
    q += __shfl_xor_sync(0xffffffffu, q, o);
  }
  float m = s * (1.f / DCH), var = q * (1.f / DCH) - m * m;
  float inv = rsqrtf(var + 1e-5f);
  float4 gw = *(const float4*)(gnw + lane * 4);
  float4 gb = *(const float4*)(gnb + lane * 4);
  float4 o4;
  o4.x = fmaxf(fmaf((v.x - m) * inv, gw.x, gb.x), 0.f);
  o4.y = fmaxf(fmaf((v.y - m) * inv, gw.y, gb.y), 0.f);
  o4.z = fmaxf(fmaf((v.z - m) * inv, gw.z, gb.z), 0.f);
  o4.w = fmaxf(fmaf((v.w - m) * inv, gw.w, gb.w), 0.f);
  *(float4*)(Y + (size_t)row * DCH + lane * 4) = o4;
}

extern "C" void kernel_launch(void* const* d_in, const int* in_sizes, int n_in,
                              void* d_out, int out_size) {
  const float* actors     = (const float*)d_in[0];
  const float* nodes      = (const float*)d_in[1];
  const float* actor_ctrs = (const float*)d_in[2];
  const float* node_ctrs  = (const float*)d_in[3];
  const int*   hi         = (const int*)d_in[4];
  const int*   wi         = (const int*)d_in[5];
  const float* Wd1   = (const float*)d_in[6];
  const float* bd1   = (const float*)d_in[7];
  const float* Wd2   = (const float*)d_in[8];
  const float* gnd2w = (const float*)d_in[9];
  const float* gnd2b = (const float*)d_in[10];
  const float* Wq    = (const float*)d_in[11];
  const float* gnqw  = (const float*)d_in[12];
  const float* gnqb  = (const float*)d_in[13];
  const float* Wc1   = (const float*)d_in[14];
  const float* gnc1w = (const float*)d_in[15];
  const float* gnc1b = (const float*)d_in[16];
  const float* Wc2   = (const float*)d_in[17];
  const float* Wa    = (const float*)d_in[18];
  const float* gnnw  = (const float*)d_in[19];
  const float* gnnb  = (const float*)d_in[20];
  const float* Wl    = (const float*)d_in[21];
  const float* gnlw  = (const float*)d_in[22];
  const float* gnlb  = (const float*)d_in[23];

  const int M = in_sizes[0] / DCH;
  const int N = in_sizes[1] / DCH;
  const int E = in_sizes[4];

  float *edge, *accb, *qc, *nc, *tmp, *agts1;
  cudaGetSymbolAddress((void**)&edge,  g_edge);
  cudaGetSymbolAddress((void**)&accb,  g_acc);
  cudaGetSymbolAddress((void**)&qc,    g_qc);
  cudaGetSymbolAddress((void**)&nc,    g_nc);
  cudaGetSymbolAddress((void**)&tmp,   g_tmp);
  cudaGetSymbolAddress((void**)&agts1, g_agts);

  cudaFuncSetAttribute(tgemm_kernel<false>, cudaFuncAttributeMaxDynamicSharedMemorySize, SMEM_DYN);
  cudaFuncSetAttribute(tgemm_kernel<true>,  cudaFuncAttributeMaxDynamicSharedMemorySize, SMEM_DYN);

  const int mb = (M + TM - 1) / TM;
  const int nb = (N + TM - 1) / TM;
  const int eb = (E + TM - 1) / TM;

  const float* agts_in = actors;
  for (int L = 0; L < 2; L++) {
    const float* Wd1L = Wd1 + L * DCH * 2;
    const float* bd1L = bd1 + L * DCH;
    const float* Wd2L = Wd2 + L * DCH * DCH;
    const float* WqL  = Wq  + L * DCH * DCH;
    const float* Wc1L = Wc1 + L * DCH * 3 * DCH;
    const float* Wc2L = Wc2 + L * DCH * DCH;
    const float* WaL  = Wa  + L * DCH * DCH;
    const float* WlL  = Wl  + L * DCH * DCH;
    float* outp = (L == 0) ? agts1 : (float*)d_out;

    GArgs a;

    // 1: tmp = relu(gn(agts @ Wq^T))
    a = GArgs{}; a.X = agts_in; a.rows = M; a.W = WqL; a.ldW = DCH; a.colOff = 0;
    a.gnw = gnqw + L * DCH; a.gnb = gnqb + L * DCH; a.relu = 1; a.Y = tmp;
    tgemm_kernel<false><<<mb, 256, SMEM_DYN>>>(a);

    // 2: qc = tmp @ Wc1[:,128:256]^T
    a = GArgs{}; a.X = tmp; a.rows = M; a.W = Wc1L; a.ldW = 3 * DCH; a.colOff = DCH;
    a.Y = qc;
    tgemm_kernel<false><<<mb, 256, SMEM_DYN>>>(a);

    // 3: nc = nodes @ Wc1[:,256:384]^T
    a = GArgs{}; a.X = nodes; a.rows = N; a.W = Wc1L; a.ldW = 3 * DCH; a.colOff = 2 * DCH;
    a.Y = nc;
    tgemm_kernel<false><<<nb, 256, SMEM_DYN>>>(a);

    // 4: acc = agts @ Wa^T
    a = GArgs{}; a.X = agts_in; a.rows = M; a.W = WaL; a.ldW = DCH; a.colOff = 0; a.Y = accb;
    tgemm_kernel<false><<<mb, 256, SMEM_DYN>>>(a);

    // 5: edge = relu(gn(relu(ctr_d @ Wd1^T + bd1) @ Wd2^T))
    a = GArgs{}; a.rows = E; a.W = Wd2L; a.ldW = DCH; a.colOff = 0;
    a.gnw = gnd2w + L * DCH; a.gnb = gnd2b + L * DCH; a.relu = 1; a.Y = edge;
    a.actor_ctrs = actor_ctrs; a.node_ctrs = node_ctrs; a.hi = hi; a.wi = wi;
    a.Wd1 = Wd1L; a.bd1 = bd1L;
    tgemm_kernel<true><<<eb, 256, SMEM_DYN>>>(a);

    // 6: edge = relu(gn(edge @ Wc1[:,0:128]^T + qc[hi] + nc[wi]))  (in-place)
    a = GArgs{}; a.X = edge; a.rows = E; a.W = Wc1L; a.ldW = 3 * DCH; a.colOff = 0;
    a.add1 = qc; a.idx1 = hi; a.add2 = nc; a.idx2 = wi;
    a.gnw = gnc1w + L * DCH; a.gnb = gnc1b + L * DCH; a.relu = 1; a.Y = edge;
    tgemm_kernel<false><<<eb, 256, SMEM_DYN>>>(a);

    // 7: acc[hi] += edge @ Wc2^T (atomic scatter)
    a = GArgs{}; a.X = edge; a.rows = E; a.W = Wc2L; a.ldW = DCH; a.colOff = 0;
    a.atomY = accb; a.atomIdx = hi;
    tgemm_kernel<false><<<eb, 256, SMEM_DYN>>>(a);

    // 8: tmp = relu(gn(acc))
    rownorm_relu_kernel<<<(M + 7) / 8, 256>>>(accb, tmp, gnnw + L * DCH, gnnb + L * DCH, M);

    // 9: out = relu(gn(tmp @ Wl^T) + agts_in)
    a = GArgs{}; a.X = tmp; a.rows = M; a.W = WlL; a.ldW = DCH; a.colOff = 0;
    a.gnw = gnlw + L * DCH; a.gnb = gnlb + L * DCH; a.relu = 0; a.res = agts_in;
    a.Y = outp;
    tgemm_kernel<false><<<mb, 256, SMEM_DYN>>>(a);

    agts_in = agts1;
  }
}

// round 5
// speedup vs baseline: 2.0377x; 1.4941x over previous
#include <cuda_runtime.h>
#include <cuda_bf16.h>
#include <cstdint>

#define DCH 128
#define TMR 64
#define LDA 68
#define LDB 68
#define OFF_A 0
#define OFF_B (TMR * LDA * 8)                  // 34816
#define OFF_S (OFF_B + 128 * LDB * 8)          // 104448
#define SMEM_SZ (OFF_S + 2048)

// ---------------- scratch (alloc-free) ----------------
__device__ float g_qc[4000 * 128];
__device__ float g_nc[20000 * 128];
__device__ float g_acc[4000 * 128];
__device__ float g_agts[4000 * 128];
__device__ uint2 g_wp[2 * 8 * 128 * 64];       // packed weights: [L][slab][j][pair]

// slabs: 0=Wq 1=Wc1a 2=Wc1b 3=Wc1c 4=Wc2 5=Wa 6=Wl 7=Wd2
#define SLAB (128 * 64)

struct P {
  const float* agts; const float* nodes;
  const float* actor_ctrs; const float* node_ctrs;
  const int* hi; const int* wi;
  const uint2* wp;
  const float* Wd1; const float* bd1;
  const float *gnq_w, *gnq_b, *gnd2_w, *gnd2_b, *gnc1_w, *gnc1_b,
              *gnn_w, *gnn_b, *gnl_w, *gnl_b;
  float *qc, *nc, *acc, *out;
  int M, N, E, mb, nb;
};

__device__ __forceinline__ uint32_t smem_u32(const void* p) {
  uint32_t a;
  asm("{ .reg .u64 t; cvta.to.shared.u64 t, %1; cvt.u32.u64 %0, t; }" : "=r"(a) : "l"(p));
  return a;
}
#define LDS64(hi, lo, addr) \
  asm volatile("ld.shared.v2.u32 {%0,%1}, [%2];" : "=r"(hi), "=r"(lo) : "r"(addr))

__device__ __forceinline__ void mma_bf16(float c[4], const uint32_t a[4],
                                         uint32_t b0, uint32_t b1) {
  asm volatile(
    "mma.sync.aligned.m16n8k16.row.col.f32.bf16.bf16.f32 "
    "{%0,%1,%2,%3}, {%4,%5,%6,%7}, {%8,%9}, {%0,%1,%2,%3};"
    : "+f"(c[0]), "+f"(c[1]), "+f"(c[2]), "+f"(c[3])
    : "r"(a[0]), "r"(a[1]), "r"(a[2]), "r"(a[3]), "r"(b0), "r"(b1));
}

__device__ __forceinline__ void pack4(float x, float y, float z, float w, uint4& out) {
  __nv_bfloat16 hx = __float2bfloat16(x), hy = __float2bfloat16(y);
  __nv_bfloat16 hz = __float2bfloat16(z), hw = __float2bfloat16(w);
  __nv_bfloat16 lx = __float2bfloat16(x - __bfloat162float(hx));
  __nv_bfloat16 ly = __float2bfloat16(y - __bfloat162float(hy));
  __nv_bfloat16 lz = __float2bfloat16(z - __bfloat162float(hz));
  __nv_bfloat16 lw = __float2bfloat16(w - __bfloat162float(hw));
  out.x = (uint32_t)__bfloat16_as_ushort(hx) | ((uint32_t)__bfloat16_as_ushort(hy) << 16);
  out.y = (uint32_t)__bfloat16_as_ushort(lx) | ((uint32_t)__bfloat16_as_ushort(ly) << 16);
  out.z = (uint32_t)__bfloat16_as_ushort(hz) | ((uint32_t)__bfloat16_as_ushort(hw) << 16);
  out.w = (uint32_t)__bfloat16_as_ushort(lz) | ((uint32_t)__bfloat16_as_ushort(lw) << 16);
}
__device__ __forceinline__ uint2 pack2(float x, float y) {
  __nv_bfloat16 hx = __float2bfloat16(x), hy = __float2bfloat16(y);
  __nv_bfloat16 lx = __float2bfloat16(x - __bfloat162float(hx));
  __nv_bfloat16 ly = __float2bfloat16(y - __bfloat162float(hy));
  uint2 o;
  o.x = (uint32_t)__bfloat16_as_ushort(hx) | ((uint32_t)__bfloat16_as_ushort(hy) << 16);
  o.y = (uint32_t)__bfloat16_as_ushort(lx) | ((uint32_t)__bfloat16_as_ushort(ly) << 16);
  return o;
}

// ---- shared building blocks ----
__device__ __forceinline__ void copy_B(char* smem, const uint2* wps) {
  const uint4* src = (const uint4*)wps;          // 4096 uint4
  for (int i = threadIdx.x; i < 4096; i += 256) {
    int j = i >> 5, p4 = (i & 31) * 2;
    *(uint4*)(smem + OFF_B + (j * LDB + p4) * 8) = src[i];
  }
}

__device__ __forceinline__ void load_A_f32(char* smem, const float* X, int row0, int rows) {
  int r = threadIdx.x >> 2, q = threadIdx.x & 3;
  int gr = row0 + r;
  const float* px = X + (size_t)gr * DCH + q * 32;
#pragma unroll
  for (int i = 0; i < 8; i++) {
    float4 v = (gr < rows) ? *(const float4*)(px + 4 * i) : make_float4(0.f, 0.f, 0.f, 0.f);
    uint4 o;
    pack4(v.x, v.y, v.z, v.w, o);
    *(uint4*)(smem + OFF_A + (r * LDA + q * 16 + 2 * i) * 8) = o;
  }
}

__device__ __forceinline__ void zero_acc(float acc[2][4][4]) {
#pragma unroll
  for (int ms = 0; ms < 2; ms++)
#pragma unroll
    for (int ns = 0; ns < 4; ns++)
#pragma unroll
      for (int q = 0; q < 4; q++) acc[ms][ns][q] = 0.f;
}

__device__ __forceinline__ void mainloop(uint32_t sb, float acc[2][4][4],
                                         int rowb, int cwb, int g, int tg) {
  const uint32_t Ab = sb + OFF_A;
  const uint32_t Bb = sb + OFF_B;
#pragma unroll
  for (int ks = 0; ks < 8; ks++) {
    uint32_t ah[2][4], al[2][4];
#pragma unroll
    for (int ms = 0; ms < 2; ms++) {
      const int r0 = rowb + ms * 16 + g;
      LDS64(ah[ms][0], al[ms][0], Ab + ((r0)     * LDA + ks * 8 + tg)     * 8);
      LDS64(ah[ms][1], al[ms][1], Ab + ((r0 + 8) * LDA + ks * 8 + tg)     * 8);
      LDS64(ah[ms][2], al[ms][2], Ab + ((r0)     * LDA + ks * 8 + tg + 4) * 8);
      LDS64(ah[ms][3], al[ms][3], Ab + ((r0 + 8) * LDA + ks * 8 + tg + 4) * 8);
    }
#pragma unroll
    for (int ns = 0; ns < 4; ns++) {
      const int n = cwb + ns * 8 + g;
      uint32_t bh0, bl0, bh1, bl1;
      LDS64(bh0, bl0, Bb + (n * LDB + ks * 8 + tg)     * 8);
      LDS64(bh1, bl1, Bb + (n * LDB + ks * 8 + tg + 4) * 8);
#pragma unroll
      for (int ms = 0; ms < 2; ms++) {
        mma_bf16(acc[ms][ns], ah[ms], bh0, bh1);
        mma_bf16(acc[ms][ns], ah[ms], bl0, bl1);
        mma_bf16(acc[ms][ns], al[ms], bh0, bh1);
      }
    }
  }
}

// GroupNorm epilogue (whole-CTA, includes one syncthreads)
__device__ __forceinline__ void gn_ep(float acc[2][4][4], char* smem,
                                      const float* gnw, const float* gnb,
                                      int rowb, int cwb, int nw, int g, int tg,
                                      bool dorelu) {
  float* ps = (float*)(smem + OFF_S);   // [4][64]
  float* pq = ps + 256;
#pragma unroll
  for (int ms = 0; ms < 2; ms++)
#pragma unroll
    for (int h = 0; h < 2; h++) {
      float s = 0.f, q = 0.f;
#pragma unroll
      for (int ns = 0; ns < 4; ns++)
#pragma unroll
        for (int j = 0; j < 2; j++) {
          float v = acc[ms][ns][2 * h + j];
          s += v;
          q = fmaf(v, v, q);
        }
      s += __shfl_xor_sync(0xffffffffu, s, 1);
      q += __shfl_xor_sync(0xffffffffu, q, 1);
      s += __shfl_xor_sync(0xffffffffu, s, 2);
      q += __shfl_xor_sync(0xffffffffu, q, 2);
      const int r = rowb + ms * 16 + h * 8 + g;
      if (tg == 0) { ps[nw * 64 + r] = s; pq[nw * 64 + r] = q; }
    }
  __syncthreads();
  const int c0 = cwb + tg * 2;
  float2 gwv[4], gbv[4];
#pragma unroll
  for (int ns = 0; ns < 4; ns++) {
    gwv[ns] = *(const float2*)(gnw + c0 + ns * 8);
    gbv[ns] = *(const float2*)(gnb + c0 + ns * 8);
  }
#pragma unroll
  for (int ms = 0; ms < 2; ms++)
#pragma unroll
    for (int h = 0; h < 2; h++) {
      const int r = rowb + ms * 16 + h * 8 + g;
      float s = ps[r] + ps[64 + r] + ps[128 + r] + ps[192 + r];
      float q = pq[r] + pq[64 + r] + pq[128 + r] + pq[192 + r];
      float m = s * (1.f / DCH);
      float var = q * (1.f / DCH) - m * m;
      float inv = rsqrtf(var + 1e-5f);
#pragma unroll
      for (int ns = 0; ns < 4; ns++) {
        float a0 = fmaf((acc[ms][ns][2 * h]     - m) * inv, gwv[ns].x, gbv[ns].x);
        float a1 = fmaf((acc[ms][ns][2 * h + 1] - m) * inv, gwv[ns].y, gbv[ns].y);
        if (dorelu) { a0 = fmaxf(a0, 0.f); a1 = fmaxf(a1, 0.f); }
        acc[ms][ns][2 * h]     = a0;
        acc[ms][ns][2 * h + 1] = a1;
      }
    }
}

__device__ __forceinline__ void repack_A(float acc[2][4][4], char* smem,
                                         int rowb, int cwb, int g, int tg) {
#pragma unroll
  for (int ms = 0; ms < 2; ms++)
#pragma unroll
    for (int h = 0; h < 2; h++) {
      const int r = rowb + ms * 16 + h * 8 + g;
#pragma unroll
      for (int ns = 0; ns < 4; ns++) {
        const int pr = (cwb >> 1) + ns * 4 + tg;
        *(uint2*)(smem + OFF_A + (r * LDA + pr) * 8) =
            pack2(acc[ms][ns][2 * h], acc[ms][ns][2 * h + 1]);
      }
    }
}

__device__ __forceinline__ void store_plain(float acc[2][4][4], float* Y, int row0, int rows,
                                            int rowb, int cwb, int g, int tg) {
  const int c0 = cwb + tg * 2;
#pragma unroll
  for (int ms = 0; ms < 2; ms++)
#pragma unroll
    for (int h = 0; h < 2; h++) {
      const int gr = row0 + rowb + ms * 16 + h * 8 + g;
      if (gr < rows) {
        float* dst = Y + (size_t)gr * DCH + c0;
#pragma unroll
        for (int ns = 0; ns < 4; ns++)
          *(float2*)(dst + ns * 8) =
              make_float2(acc[ms][ns][2 * h], acc[ms][ns][2 * h + 1]);
      }
    }
}

// ---------------- weight pack ----------------
__global__ void wpack_kernel(const float* Wq, const float* Wc1, const float* Wc2,
                             const float* Wa, const float* Wl, const float* Wd2,
                             uint2* wp) {
  int L = blockIdx.x >> 3, s = blockIdx.x & 7;
  const float* src;
  int ldw = DCH, coff = 0;
  switch (s) {
    case 0: src = Wq  + (size_t)L * DCH * DCH; break;
    case 1: src = Wc1 + (size_t)L * DCH * 3 * DCH; ldw = 3 * DCH; coff = 0;        break;
    case 2: src = Wc1 + (size_t)L * DCH * 3 * DCH; ldw = 3 * DCH; coff = DCH;      break;
    case 3: src = Wc1 + (size_t)L * DCH * 3 * DCH; ldw = 3 * DCH; coff = 2 * DCH;  break;
    case 4: src = Wc2 + (size_t)L * DCH * DCH; break;
    case 5: src = Wa  + (size_t)L * DCH * DCH; break;
    case 6: src = Wl  + (size_t)L * DCH * DCH; break;
    default: src = Wd2 + (size_t)L * DCH * DCH; break;
  }
  uint2* dst = wp + (size_t)(L * 8 + s) * SLAB;
  int j = threadIdx.x >> 1, half = threadIdx.x & 1;
  const float* p = src + (size_t)j * ldw + coff + half * 64;
  uint2* drow = dst + j * 64 + half * 32;
#pragma unroll
  for (int i = 0; i < 16; i++) {
    float4 v = *(const float4*)(p + 4 * i);
    uint4 o;
    pack4(v.x, v.y, v.z, v.w, o);
    *(uint4*)(drow + 2 * i) = o;
  }
}

// ---------------- MN mega-kernel: {1+2 fused | 3 | 4} ----------------
__global__ void __launch_bounds__(256, 2) mn_kernel(P p) {
  extern __shared__ char smem[];
  const uint32_t sb = smem_u32(smem);
  const int tid = threadIdx.x, warp = tid >> 5, lane = tid & 31;
  const int mw = warp & 1, nw = warp >> 1;
  const int rowb = mw * 32, cwb = nw * 32, g = lane >> 2, tg = lane & 3;
  const int b = blockIdx.x;
  float acc[2][4][4];

  if (b < p.mb) {
    const int row0 = b * TMR;
    load_A_f32(smem, p.agts, row0, p.M);
    copy_B(smem, p.wp + 0 * SLAB);               // Wq
    __syncthreads();
    zero_acc(acc);
    mainloop(sb, acc, rowb, cwb, g, tg);
    gn_ep(acc, smem, p.gnq_w, p.gnq_b, rowb, cwb, nw, g, tg, true);
    repack_A(acc, smem, rowb, cwb, g, tg);
    copy_B(smem, p.wp + 2 * SLAB);               // Wc1b
    __syncthreads();
    zero_acc(acc);
    mainloop(sb, acc, rowb, cwb, g, tg);
    store_plain(acc, p.qc, row0, p.M, rowb, cwb, g, tg);
  } else if (b < p.mb + p.nb) {
    const int row0 = (b - p.mb) * TMR;
    load_A_f32(smem, p.nodes, row0, p.N);
    copy_B(smem, p.wp + 3 * SLAB);               // Wc1c
    __syncthreads();
    zero_acc(acc);
    mainloop(sb, acc, rowb, cwb, g, tg);
    store_plain(acc, p.nc, row0, p.N, rowb, cwb, g, tg);
  } else {
    const int row0 = (b - p.mb - p.nb) * TMR;
    load_A_f32(smem, p.agts, row0, p.M);
    copy_B(smem, p.wp + 5 * SLAB);               // Wa
    __syncthreads();
    zero_acc(acc);
    mainloop(sb, acc, rowb, cwb, g, tg);
    store_plain(acc, p.acc, row0, p.M, rowb, cwb, g, tg);
  }
}

// ---------------- E kernel: fused 5 -> 6 -> 7 ----------------
__global__ void __launch_bounds__(256, 2) e_kernel(P p) {
  extern __shared__ char smem[];
  const uint32_t sb = smem_u32(smem);
  const int tid = threadIdx.x, warp = tid >> 5, lane = tid & 31;
  const int mw = warp & 1, nw = warp >> 1;
  const int rowb = mw * 32, cwb = nw * 32, g = lane >> 2, tg = lane & 3;
  const int row0 = blockIdx.x * TMR;
  float acc[2][4][4];

  // ---- stage 1: A = relu(ctr_d @ Wd1^T + bd1), B = Wd2 ----
  {
    const int r = tid >> 2, q = tid & 3;
    const int gr = row0 + r;
    float cx = 0.f, cy = 0.f;
    if (gr < p.E) {
      int h = p.hi[gr], w = p.wi[gr];
      cx = p.actor_ctrs[2 * h]     - p.node_ctrs[2 * w];
      cy = p.actor_ctrs[2 * h + 1] - p.node_ctrs[2 * w + 1];
    }
#pragma unroll
    for (int i = 0; i < 8; i++) {
      float vv[4];
#pragma unroll
      for (int j = 0; j < 4; j++) {
        const int k = q * 32 + 4 * i + j;
        vv[j] = fmaxf(fmaf(cx, p.Wd1[2 * k], fmaf(cy, p.Wd1[2 * k + 1], p.bd1[k])), 0.f);
      }
      uint4 o;
      pack4(vv[0], vv[1], vv[2], vv[3], o);
      *(uint4*)(smem + OFF_A + (r * LDA + q * 16 + 2 * i) * 8) = o;
    }
  }
  copy_B(smem, p.wp + 7 * SLAB);                 // Wd2
  __syncthreads();
  zero_acc(acc);
  mainloop(sb, acc, rowb, cwb, g, tg);
  gn_ep(acc, smem, p.gnd2_w, p.gnd2_b, rowb, cwb, nw, g, tg, true);
  repack_A(acc, smem, rowb, cwb, g, tg);
  copy_B(smem, p.wp + 1 * SLAB);                 // Wc1a
  __syncthreads();

  // ---- stage 2: + qc[hi] + nc[wi], gn, relu ----
  zero_acc(acc);
  mainloop(sb, acc, rowb, cwb, g, tg);
  {
    const int c0 = cwb + tg * 2;
#pragma unroll
    for (int ms = 0; ms < 2; ms++)
#pragma unroll
      for (int h = 0; h < 2; h++) {
        const int gr = row0 + rowb + ms * 16 + h * 8 + g;
        if (gr < p.E) {
          const float* p1 = p.qc + (size_t)p.hi[gr] * DCH + c0;
          const float* p2 = p.nc + (size_t)p.wi[gr] * DCH + c0;
#pragma unroll
          for (int ns = 0; ns < 4; ns++) {
            float2 v1 = *(const float2*)(p1 + ns * 8);
            float2 v2 = *(const float2*)(p2 + ns * 8);
            acc[ms][ns][2 * h]     += v1.x + v2.x;
            acc[ms][ns][2 * h + 1] += v1.y + v2.y;
          }
        }
      }
  }
  gn_ep(acc, smem, p.gnc1_w, p.gnc1_b, rowb, cwb, nw, g, tg, true);
  repack_A(acc, smem, rowb, cwb, g, tg);
  copy_B(smem, p.wp + 4 * SLAB);                 // Wc2
  __syncthreads();

  // ---- stage 3: atomic scatter acc[hi] += cf @ Wc2^T ----
  zero_acc(acc);
  mainloop(sb, acc, rowb, cwb, g, tg);
  {
    const int c0 = cwb + tg * 2;
#pragma unroll
    for (int ms = 0; ms < 2; ms++)
#pragma unroll
      for (int h = 0; h < 2; h++) {
        const int gr = row0 + rowb + ms * 16 + h * 8 + g;
        if (gr < p.E) {
          float* dst = p.acc + (size_t)p.hi[gr] * DCH + c0;
#pragma unroll
          for (int ns = 0; ns < 4; ns++) {
            atomicAdd(dst + ns * 8,     acc[ms][ns][2 * h]);
            atomicAdd(dst + ns * 8 + 1, acc[ms][ns][2 * h + 1]);
          }
        }
      }
  }
}

// ---------------- F kernel: fused relu(gn(acc)) -> GEMM Wl -> gn + res + relu ----
__global__ void __launch_bounds__(256, 2) f_kernel(P p) {
  extern __shared__ char smem[];
  const uint32_t sb = smem_u32(smem);
  const int tid = threadIdx.x, warp = tid >> 5, lane = tid & 31;
  const int mw = warp & 1, nw = warp >> 1;
  const int rowb = mw * 32, cwb = nw * 32, g = lane >> 2, tg = lane & 3;
  const int row0 = blockIdx.x * TMR;
  float acc[2][4][4];

  // load A = relu(gn(acc_row)) with gnn params
  {
    const int r = tid >> 2, q = tid & 3;
    const int gr = row0 + r;
    float v[32];
    const float* px = p.acc + (size_t)gr * DCH + q * 32;
#pragma unroll
    for (int i = 0; i < 8; i++) {
      float4 t = (gr < p.M) ? *(const float4*)(px + 4 * i) : make_float4(0.f, 0.f, 0.f, 0.f);
      v[4 * i] = t.x; v[4 * i + 1] = t.y; v[4 * i + 2] = t.z; v[4 * i + 3] = t.w;
    }
    float s = 0.f, qq = 0.f;
#pragma unroll
    for (int i = 0; i < 32; i++) { s += v[i]; qq = fmaf(v[i], v[i], qq); }
    s  += __shfl_xor_sync(0xffffffffu, s, 1);
    qq += __shfl_xor_sync(0xffffffffu, qq, 1);
    s  += __shfl_xor_sync(0xffffffffu, s, 2);
    qq += __shfl_xor_sync(0xffffffffu, qq, 2);
    float m = s * (1.f / DCH);
    float var = qq * (1.f / DCH) - m * m;
    float inv = rsqrtf(var + 1e-5f);
#pragma unroll
    for (int i = 0; i < 32; i++) {
      const int c = q * 32 + i;
      v[i] = fmaxf(fmaf((v[i] - m) * inv, p.gnn_w[c], p.gnn_b[c]), 0.f);
    }
#pragma unroll
    for (int i = 0; i < 8; i++) {
      uint4 o;
      pack4(v[4 * i], v[4 * i + 1], v[4 * i + 2], v[4 * i + 3], o);
      *(uint4*)(smem + OFF_A + (r * LDA + q * 16 + 2 * i) * 8) = o;
    }
  }
  copy_B(smem, p.wp + 6 * SLAB);                 // Wl
  __syncthreads();
  zero_acc(acc);
  mainloop(sb, acc, rowb, cwb, g, tg);
  gn_ep(acc, smem, p.gnl_w, p.gnl_b, rowb, cwb, nw, g, tg, false);
  {
    const int c0 = cwb + tg * 2;
#pragma unroll
    for (int ms = 0; ms < 2; ms++)
#pragma unroll
      for (int h = 0; h < 2; h++) {
        const int gr = row0 + rowb + ms * 16 + h * 8 + g;
        if (gr < p.M) {
          const float* rp = p.agts + (size_t)gr * DCH + c0;
          float* dst = p.out + (size_t)gr * DCH + c0;
#pragma unroll
          for (int ns = 0; ns < 4; ns++) {
            float2 rv = *(const float2*)(rp + ns * 8);
            *(float2*)(dst + ns * 8) =
                make_float2(fmaxf(acc[ms][ns][2 * h]     + rv.x, 0.f),
                            fmaxf(acc[ms][ns][2 * h + 1] + rv.y, 0.f));
          }
        }
      }
  }
}

extern "C" void kernel_launch(void* const* d_in, const int* in_sizes, int n_in,
                              void* d_out, int out_size) {
  const float* actors     = (const float*)d_in[0];
  const float* nodes      = (const float*)d_in[1];
  const float* actor_ctrs = (const float*)d_in[2];
  const float* node_ctrs  = (const float*)d_in[3];
  const int*   hi         = (const int*)d_in[4];
  const int*   wi         = (const int*)d_in[5];
  const float* Wd1   = (const float*)d_in[6];
  const float* bd1   = (const float*)d_in[7];
  const float* Wd2   = (const float*)d_in[8];
  const float* gnd2w = (const float*)d_in[9];
  const float* gnd2b = (const float*)d_in[10];
  const float* Wq    = (const float*)d_in[11];
  const float* gnqw  = (const float*)d_in[12];
  const float* gnqb  = (const float*)d_in[13];
  const float* Wc1   = (const float*)d_in[14];
  const float* gnc1w = (const float*)d_in[15];
  const float* gnc1b = (const float*)d_in[16];
  const float* Wc2   = (const float*)d_in[17];
  const float* Wa    = (const float*)d_in[18];
  const float* gnnw  = (const float*)d_in[19];
  const float* gnnb  = (const float*)d_in[20];
  const float* Wl    = (const float*)d_in[21];
  const float* gnlw  = (const float*)d_in[22];
  const float* gnlb  = (const float*)d_in[23];

  const int M = in_sizes[0] / DCH;
  const int N = in_sizes[1] / DCH;
  const int E = in_sizes[4];

  float *qc, *nc, *accb, *agts1;
  uint2* wp;
  cudaGetSymbolAddress((void**)&qc,    g_qc);
  cudaGetSymbolAddress((void**)&nc,    g_nc);
  cudaGetSymbolAddress((void**)&accb,  g_acc);
  cudaGetSymbolAddress((void**)&agts1, g_agts);
  cudaGetSymbolAddress((void**)&wp,    g_wp);

  cudaFuncSetAttribute(mn_kernel, cudaFuncAttributeMaxDynamicSharedMemorySize, SMEM_SZ);
  cudaFuncSetAttribute(e_kernel,  cudaFuncAttributeMaxDynamicSharedMemorySize, SMEM_SZ);
  cudaFuncSetAttribute(f_kernel,  cudaFuncAttributeMaxDynamicSharedMemorySize, SMEM_SZ);

  const int mb = (M + TMR - 1) / TMR;
  const int nb = (N + TMR - 1) / TMR;
  const int eb = (E + TMR - 1) / TMR;

  wpack_kernel<<<16, 256>>>(Wq, Wc1, Wc2, Wa, Wl, Wd2, wp);

  const float* agts_in = actors;
  for (int L = 0; L < 2; L++) {
    P p = {};
    p.agts = agts_in;
    p.nodes = nodes;
    p.actor_ctrs = actor_ctrs;
    p.node_ctrs = node_ctrs;
    p.hi = hi;
    p.wi = wi;
    p.wp = wp + (size_t)L * 8 * SLAB;
    p.Wd1 = Wd1 + L * DCH * 2;
    p.bd1 = bd1 + L * DCH;
    p.gnq_w = gnqw + L * DCH;   p.gnq_b = gnqb + L * DCH;
    p.gnd2_w = gnd2w + L * DCH; p.gnd2_b = gnd2b + L * DCH;
    p.gnc1_w = gnc1w + L * DCH; p.gnc1_b = gnc1b + L * DCH;
    p.gnn_w = gnnw + L * DCH;   p.gnn_b = gnnb + L * DCH;
    p.gnl_w = gnlw + L * DCH;   p.gnl_b = gnlb + L * DCH;
    p.qc = qc; p.nc = nc; p.acc = accb;
    p.out = (L == 0) ? agts1 : (float*)d_out;
    p.M = M; p.N = N; p.E = E; p.mb = mb; p.nb = nb;

    mn_kernel<<<mb + nb + mb, 256, SMEM_SZ>>>(p);
    e_kernel<<<eb, 256, SMEM_SZ>>>(p);
    f_kernel<<<mb, 256, SMEM_SZ>>>(p);

    agts_in = agts1;
  }
}